// round 1
// baseline (speedup 1.0000x reference)
#include <cuda_runtime.h>
#include <cuda_bf16.h>

// Problem constants (fixed by reference)
#define VOCAB      32000
#define EMBED_DIM  128
#define BATCH      32
#define MAX_TREES  512
#define NSEG       (BATCH * MAX_TREES)   // 16384

// Scratch: segment boundaries (device global — allocation-free)
__device__ int g_seg_start[NSEG + 1];

// ---------------------------------------------------------------------------
// Kernel 1: binary-search segment boundaries in the sorted tree_ids array.
// g_seg_start[s] = lower_bound(tree_ids, s); g_seg_start[NSEG] = n.
// ---------------------------------------------------------------------------
__global__ void seg_bounds_kernel(const int* __restrict__ tree_ids, int n) {
    int s = blockIdx.x * blockDim.x + threadIdx.x;
    if (s > NSEG) return;
    int lo = 0, hi = n;
    while (lo < hi) {
        int mid = (lo + hi) >> 1;
        if (__ldg(&tree_ids[mid]) < s) lo = mid + 1;
        else hi = mid;
    }
    g_seg_start[s] = lo;
}

// ---------------------------------------------------------------------------
// Kernel 2: one warp per segment. 32 lanes x float4 = full 128-float row.
// Each lane accumulates 4 floats for the key table and 4 for the value table.
// Embedding row reads are fully coalesced 512B (L2-resident tables).
// ---------------------------------------------------------------------------
__global__ void __launch_bounds__(256, 8)
seg_sum_kernel(const int*    __restrict__ token_ids,
               const float4* __restrict__ C_hop,    // [VOCAB][32] float4
               const float4* __restrict__ C_hop1,
               float4*       __restrict__ out)      // [2][NSEG][32] float4
{
    const int warp = (blockIdx.x * blockDim.x + threadIdx.x) >> 5;
    const int lane = threadIdx.x & 31;
    if (warp >= NSEG) return;

    const int beg = g_seg_start[warp];
    const int end = g_seg_start[warp + 1];

    float4 ak = make_float4(0.f, 0.f, 0.f, 0.f);
    float4 av = make_float4(0.f, 0.f, 0.f, 0.f);

    int i = beg;
    // Unroll by 4 to get 8 independent 16B loads in flight per lane (hide L2 lat)
    for (; i + 4 <= end; i += 4) {
        int t0 = __ldg(&token_ids[i + 0]);
        int t1 = __ldg(&token_ids[i + 1]);
        int t2 = __ldg(&token_ids[i + 2]);
        int t3 = __ldg(&token_ids[i + 3]);

        float4 k0 = __ldg(&C_hop [t0 * 32 + lane]);
        float4 v0 = __ldg(&C_hop1[t0 * 32 + lane]);
        float4 k1 = __ldg(&C_hop [t1 * 32 + lane]);
        float4 v1 = __ldg(&C_hop1[t1 * 32 + lane]);
        float4 k2 = __ldg(&C_hop [t2 * 32 + lane]);
        float4 v2 = __ldg(&C_hop1[t2 * 32 + lane]);
        float4 k3 = __ldg(&C_hop [t3 * 32 + lane]);
        float4 v3 = __ldg(&C_hop1[t3 * 32 + lane]);

        ak.x += k0.x; ak.y += k0.y; ak.z += k0.z; ak.w += k0.w;
        av.x += v0.x; av.y += v0.y; av.z += v0.z; av.w += v0.w;
        ak.x += k1.x; ak.y += k1.y; ak.z += k1.z; ak.w += k1.w;
        av.x += v1.x; av.y += v1.y; av.z += v1.z; av.w += v1.w;
        ak.x += k2.x; ak.y += k2.y; ak.z += k2.z; ak.w += k2.w;
        av.x += v2.x; av.y += v2.y; av.z += v2.z; av.w += v2.w;
        ak.x += k3.x; ak.y += k3.y; ak.z += k3.z; ak.w += k3.w;
        av.x += v3.x; av.y += v3.y; av.z += v3.z; av.w += v3.w;
    }
    for (; i < end; i++) {
        int t = __ldg(&token_ids[i]);
        float4 k = __ldg(&C_hop [t * 32 + lane]);
        float4 v = __ldg(&C_hop1[t * 32 + lane]);
        ak.x += k.x; ak.y += k.y; ak.z += k.z; ak.w += k.w;
        av.x += v.x; av.y += v.y; av.z += v.z; av.w += v.w;
    }

    // out layout: [2, NSEG, 32 float4]; key plane first, then value plane.
    out[(size_t)warp * 32 + lane]                         = ak;
    out[(size_t)NSEG * 32 + (size_t)warp * 32 + lane]     = av;
}

// ---------------------------------------------------------------------------
// Launch
// ---------------------------------------------------------------------------
extern "C" void kernel_launch(void* const* d_in, const int* in_sizes, int n_in,
                              void* d_out, int out_size) {
    const int*    token_ids = (const int*)   d_in[0];
    const int*    tree_ids  = (const int*)   d_in[1];
    const float4* C_hop     = (const float4*)d_in[2];
    const float4* C_hop1    = (const float4*)d_in[3];
    float4*       out       = (float4*)      d_out;

    const int n = in_sizes[0];  // TOTAL_TOKENS

    // Kernel 1: segment boundaries (16385 searches)
    {
        int threads = 256;
        int blocks  = (NSEG + 1 + threads - 1) / threads;
        seg_bounds_kernel<<<blocks, threads>>>(tree_ids, n);
    }

    // Kernel 2: one warp per segment -> 16384 warps = 2048 blocks x 256 threads
    {
        int threads = 256;
        int blocks  = (NSEG * 32 + threads - 1) / threads;  // 2048
        seg_sum_kernel<<<blocks, threads>>>(token_ids, C_hop, C_hop1, out);
    }
}